// round 1
// baseline (speedup 1.0000x reference)
#include <cuda_runtime.h>
#include <math.h>

#define BATCH 2
#define SEQ   4096
#define DM    512
#define NH    8
#define DH    64
#define MTOT  (BATCH*SEQ)   // 8192

// Scratch (no cudaMalloc allowed): projected Q/K/V in [B,H,S,Dh], attn out in [B,S,D]
__device__ float g_Qp[BATCH*NH*SEQ*DH];
__device__ float g_Kp[BATCH*NH*SEQ*DH];
__device__ float g_Vp[BATCH*NH*SEQ*DH];
__device__ float g_At[BATCH*SEQ*DM];

// ---------------------------------------------------------------------------
// NT GEMM: C[m][n] = sum_k A[m][k] * B[n][k],  K = N = 512, M = 8192
// 128x128 block tile, BK=16, 256 threads, 8x8 microtile.
// asel: 0 -> A = Ain, 1 -> A = g_At
// osel: 0 -> C = Cout (row-major [m][n]); 1/2/3 -> g_Qp/g_Kp/g_Vp with
//       [B,H,S,Dh] remap epilogue.
// ---------------------------------------------------------------------------
__global__ __launch_bounds__(256, 2)
void gemm_nt(const float* __restrict__ Ain, const float* __restrict__ B,
             float* __restrict__ Cout, int asel, int osel)
{
    __shared__ float sA[16][129];
    __shared__ float sB[16][129];

    const float* A = asel ? g_At : Ain;
    float* C;
    if      (osel == 1) C = g_Qp;
    else if (osel == 2) C = g_Kp;
    else if (osel == 3) C = g_Vp;
    else                C = Cout;

    const int tid = threadIdx.x;
    const int tx = tid & 15, ty = tid >> 4;
    const int m0 = blockIdx.x << 7;
    const int n0 = blockIdx.y << 7;

    float acc[8][8];
#pragma unroll
    for (int i = 0; i < 8; i++)
#pragma unroll
        for (int j = 0; j < 8; j++) acc[i][j] = 0.f;

    for (int kb = 0; kb < 512; kb += 16) {
#pragma unroll
        for (int r = 0; r < 2; r++) {
            int idx = tid + (r << 8);        // 0..511
            int row = idx >> 2;              // 0..127
            int c4  = (idx & 3) << 2;        // 0,4,8,12
            float4 va = *(const float4*)(A + (size_t)(m0 + row) * 512 + kb + c4);
            sA[c4+0][row] = va.x; sA[c4+1][row] = va.y;
            sA[c4+2][row] = va.z; sA[c4+3][row] = va.w;
            float4 vb = *(const float4*)(B + (size_t)(n0 + row) * 512 + kb + c4);
            sB[c4+0][row] = vb.x; sB[c4+1][row] = vb.y;
            sB[c4+2][row] = vb.z; sB[c4+3][row] = vb.w;
        }
        __syncthreads();
#pragma unroll
        for (int kk = 0; kk < 16; kk++) {
            float a[8], b[8];
#pragma unroll
            for (int i = 0; i < 8; i++) a[i] = sA[kk][ty + (i << 4)];
#pragma unroll
            for (int j = 0; j < 8; j++) b[j] = sB[kk][tx + (j << 4)];
#pragma unroll
            for (int i = 0; i < 8; i++)
#pragma unroll
                for (int j = 0; j < 8; j++)
                    acc[i][j] = fmaf(a[i], b[j], acc[i][j]);
        }
        __syncthreads();
    }

#pragma unroll
    for (int i = 0; i < 8; i++) {
        int m = m0 + ty + (i << 4);
#pragma unroll
        for (int j = 0; j < 8; j++) {
            int n = n0 + tx + (j << 4);
            if (osel == 0) {
                C[(size_t)m * 512 + n] = acc[i][j];
            } else {
                int b = m >> 12, s = m & 4095;   // m = b*4096 + s
                int h = n >> 6,  d = n & 63;     // n = h*64 + d
                C[(((size_t)(b * NH + h)) * SEQ + s) * DH + d] = acc[i][j];
            }
        }
    }
}

// ---------------------------------------------------------------------------
// Causal flash attention, fp32. One CTA = 64 queries of one (b,h).
// BQ=64, BK=64, 256 threads (16x16), 4x4 microtiles. Online softmax in exp2
// domain. P tile overwrites K tile smem. Dynamic smem: 2*(64*65) + 64*64 fl.
// Reads g_Qp/g_Kp/g_Vp, writes g_At in [B,S,H*Dh].
// ---------------------------------------------------------------------------
__global__ __launch_bounds__(256)
void flash_causal()
{
    extern __shared__ float sm[];
    float* Qs = sm;                 // [64][65]
    float* KP = sm + 64 * 65;       // [64][65]  (K tile, then P tile)
    float* Vs = sm + 2 * 64 * 65;   // [64][64]

    const int tid = threadIdx.x;
    const int tx = tid & 15, ty = tid >> 4;
    const int qb = blockIdx.x;
    const int bh = blockIdx.y;
    const int q0 = qb << 6;

    const float* Q = g_Qp + (size_t)bh * SEQ * DH;
    const float* K = g_Kp + (size_t)bh * SEQ * DH;
    const float* V = g_Vp + (size_t)bh * SEQ * DH;

    // Load Q tile (64 x 64)
    for (int idx = tid; idx < 64 * 16; idx += 256) {
        int row = idx >> 4, c4 = (idx & 15) << 2;
        float4 vq = *(const float4*)(Q + (size_t)(q0 + row) * DH + c4);
        Qs[row * 65 + c4 + 0] = vq.x; Qs[row * 65 + c4 + 1] = vq.y;
        Qs[row * 65 + c4 + 2] = vq.z; Qs[row * 65 + c4 + 3] = vq.w;
    }

    float o[4][4];
#pragma unroll
    for (int i = 0; i < 4; i++)
#pragma unroll
        for (int j = 0; j < 4; j++) o[i][j] = 0.f;
    float mrow[4], lrow[4];
#pragma unroll
    for (int i = 0; i < 4; i++) { mrow[i] = -1e30f; lrow[i] = 0.f; }

    const float cscale = 0.125f * 1.4426950408889634f;  // 1/sqrt(64) * log2(e)

    for (int kt = 0; kt <= qb; kt++) {
        const int k0 = kt << 6;
        __syncthreads();   // previous P/V reads done before overwrite
        for (int idx = tid; idx < 64 * 16; idx += 256) {
            int row = idx >> 4, c4 = (idx & 15) << 2;
            float4 vk = *(const float4*)(K + (size_t)(k0 + row) * DH + c4);
            KP[row * 65 + c4 + 0] = vk.x; KP[row * 65 + c4 + 1] = vk.y;
            KP[row * 65 + c4 + 2] = vk.z; KP[row * 65 + c4 + 3] = vk.w;
            float4 vv = *(const float4*)(V + (size_t)(k0 + row) * DH + c4);
            *(float4*)(Vs + row * 64 + c4) = vv;
        }
        __syncthreads();

        // S = Q @ K^T
        float s[4][4];
#pragma unroll
        for (int i = 0; i < 4; i++)
#pragma unroll
            for (int j = 0; j < 4; j++) s[i][j] = 0.f;
#pragma unroll 8
        for (int kk = 0; kk < 64; kk++) {
            float a[4], b[4];
#pragma unroll
            for (int i = 0; i < 4; i++) a[i] = Qs[(ty + (i << 4)) * 65 + kk];
#pragma unroll
            for (int j = 0; j < 4; j++) b[j] = KP[(tx + (j << 4)) * 65 + kk];
#pragma unroll
            for (int i = 0; i < 4; i++)
#pragma unroll
                for (int j = 0; j < 4; j++)
                    s[i][j] = fmaf(a[i], b[j], s[i][j]);
        }

        // scale (exp2 domain) + causal mask on diagonal tile
#pragma unroll
        for (int i = 0; i < 4; i++)
#pragma unroll
            for (int j = 0; j < 4; j++) s[i][j] *= cscale;
        if (kt == qb) {
#pragma unroll
            for (int i = 0; i < 4; i++) {
                int qg = q0 + ty + (i << 4);
#pragma unroll
                for (int j = 0; j < 4; j++) {
                    int kg = k0 + tx + (j << 4);
                    if (kg > qg) s[i][j] = -1e30f;
                }
            }
        }

        // online softmax update (row stats reduced across the 16-lane group)
#pragma unroll
        for (int i = 0; i < 4; i++) {
            float mx = fmaxf(fmaxf(s[i][0], s[i][1]), fmaxf(s[i][2], s[i][3]));
            mx = fmaxf(mx, __shfl_xor_sync(0xffffffffu, mx, 8));
            mx = fmaxf(mx, __shfl_xor_sync(0xffffffffu, mx, 4));
            mx = fmaxf(mx, __shfl_xor_sync(0xffffffffu, mx, 2));
            mx = fmaxf(mx, __shfl_xor_sync(0xffffffffu, mx, 1));
            float mn = fmaxf(mrow[i], mx);
            float al = exp2f(mrow[i] - mn);
            mrow[i] = mn;
            float rs = 0.f;
#pragma unroll
            for (int j = 0; j < 4; j++) {
                float p = exp2f(s[i][j] - mn);
                s[i][j] = p;
                rs += p;
            }
            rs += __shfl_xor_sync(0xffffffffu, rs, 8);
            rs += __shfl_xor_sync(0xffffffffu, rs, 4);
            rs += __shfl_xor_sync(0xffffffffu, rs, 2);
            rs += __shfl_xor_sync(0xffffffffu, rs, 1);
            lrow[i] = lrow[i] * al + rs;
#pragma unroll
            for (int j = 0; j < 4; j++) o[i][j] *= al;
        }

        __syncthreads();   // all K-tile reads done before P overwrite
#pragma unroll
        for (int i = 0; i < 4; i++)
#pragma unroll
            for (int j = 0; j < 4; j++)
                KP[(ty + (i << 4)) * 65 + tx + (j << 4)] = s[i][j];
        __syncthreads();

        // O += P @ V
#pragma unroll 8
        for (int kk = 0; kk < 64; kk++) {
            float a[4], b[4];
#pragma unroll
            for (int i = 0; i < 4; i++) a[i] = KP[(ty + (i << 4)) * 65 + kk];
#pragma unroll
            for (int j = 0; j < 4; j++) b[j] = Vs[kk * 64 + tx + (j << 4)];
#pragma unroll
            for (int i = 0; i < 4; i++)
#pragma unroll
                for (int j = 0; j < 4; j++)
                    o[i][j] = fmaf(a[i], b[j], o[i][j]);
        }
    }

    // epilogue -> g_At in [B, S, H*Dh]
    const int b = bh >> 3, h = bh & 7;
#pragma unroll
    for (int i = 0; i < 4; i++) {
        float inv = 1.f / lrow[i];
        int qg = q0 + ty + (i << 4);
#pragma unroll
        for (int j = 0; j < 4; j++) {
            int d = tx + (j << 4);
            g_At[((size_t)b * SEQ + qg) * DM + h * DH + d] = o[i][j] * inv;
        }
    }
}

// ---------------------------------------------------------------------------
extern "C" void kernel_launch(void* const* d_in, const int* in_sizes, int n_in,
                              void* d_out, int out_size)
{
    const float* q  = (const float*)d_in[0];
    const float* k  = (const float*)d_in[1];
    const float* v  = (const float*)d_in[2];
    const float* wq = (const float*)d_in[3];
    const float* wk = (const float*)d_in[4];
    const float* wv = (const float*)d_in[5];
    const float* wo = (const float*)d_in[6];
    float* out = (float*)d_out;

    const int FLASH_SMEM = (2 * 64 * 65 + 64 * 64) * (int)sizeof(float); // 49664B
    cudaFuncSetAttribute(flash_causal, cudaFuncAttributeMaxDynamicSharedMemorySize,
                         FLASH_SMEM);

    dim3 pg(MTOT / 128, DM / 128);   // 64 x 4
    gemm_nt<<<pg, 256>>>(q, wq, nullptr, 0, 1);   // -> g_Qp
    gemm_nt<<<pg, 256>>>(k, wk, nullptr, 0, 2);   // -> g_Kp
    gemm_nt<<<pg, 256>>>(v, wv, nullptr, 0, 3);   // -> g_Vp

    dim3 fg(SEQ / 64, BATCH * NH);   // 64 x 16
    flash_causal<<<fg, 256, FLASH_SMEM>>>();

    gemm_nt<<<pg, 256>>>(nullptr, wo, out, 1, 0); // g_At @ wo^T -> out
}

// round 2
// speedup vs baseline: 3.5738x; 3.5738x over previous
#include <cuda_runtime.h>

#define BATCH 2
#define SEQ   4096
#define DM    512
#define NH    8
#define DH    64
#define MTOT  (BATCH*SEQ)   // 8192

// Scratch (no cudaMalloc): projected Q/K/V (tf32-rounded fp32 bits) in [B,H,S,Dh],
// attention output (plain fp32) in [B,S,D]
__device__ float g_Qp[BATCH*NH*SEQ*DH];
__device__ float g_Kp[BATCH*NH*SEQ*DH];
__device__ float g_Vp[BATCH*NH*SEQ*DH];
__device__ float g_At[BATCH*SEQ*DM];

// ---------------------------------------------------------------------------
// helpers
// ---------------------------------------------------------------------------
__device__ __forceinline__ unsigned f2tf(float f) {
    unsigned u;
    asm("cvt.rna.tf32.f32 %0, %1;" : "=r"(u) : "f"(f));
    return u;
}
__device__ __forceinline__ float ex2_(float x) {
    float y;
    asm("ex2.approx.f32 %0, %1;" : "=f"(y) : "f"(x));
    return y;
}
// D += A(16x8) * B(8x8), tf32, row.col. d: 4 f32; a: 4 u32; b: 2 u32.
__device__ __forceinline__ void mma_tf32(float* d, const unsigned* a,
                                         unsigned b0, unsigned b1) {
    asm volatile(
        "mma.sync.aligned.m16n8k8.row.col.f32.tf32.tf32.f32 "
        "{%0,%1,%2,%3}, {%4,%5,%6,%7}, {%8,%9}, {%0,%1,%2,%3};\n"
        : "+f"(d[0]), "+f"(d[1]), "+f"(d[2]), "+f"(d[3])
        : "r"(a[0]), "r"(a[1]), "r"(a[2]), "r"(a[3]), "r"(b0), "r"(b1));
}

// ---------------------------------------------------------------------------
// GEMM body: C[m][n] = sum_k A[m][k] * B[n][k];  M rows from grid.x, N=K=512.
// 128x128 tile, BK=32, 128 threads = 4 warps (2x2), warp tile 64x64.
// OSEL 0: plain fp32 store to C[m*512+n].
// OSEL 1: tf32-round + remap store to C[((b*NH+h)*SEQ+s)*DH+d].
// ---------------------------------------------------------------------------
template <int OSEL>
__device__ __forceinline__ void gemm_body(const float* __restrict__ A,
                                          const float* __restrict__ B,
                                          float* __restrict__ C)
{
    __shared__ float sA[128][36];
    __shared__ float sB[128][36];

    const int tid = threadIdx.x;
    const int lane = tid & 31, wid = tid >> 5;
    const int group = lane >> 2, tq = lane & 3;
    const int wm = wid & 1, wn = wid >> 1;          // 2x2 warp grid
    const int m0 = blockIdx.x << 7;
    const int n0 = blockIdx.y << 7;

    float acc[4][8][4];
#pragma unroll
    for (int mt = 0; mt < 4; mt++)
#pragma unroll
        for (int nt = 0; nt < 8; nt++)
#pragma unroll
            for (int c = 0; c < 4; c++) acc[mt][nt][c] = 0.f;

    const int r0 = tid >> 3;            // 0..15
    const int c4 = (tid & 7) << 2;      // 0..28 step 4

    for (int kb = 0; kb < 512; kb += 32) {
#pragma unroll
        for (int rr = 0; rr < 8; rr++) {
            int row = r0 + (rr << 4);
            float4 va = *(const float4*)(A + (size_t)(m0 + row) * 512 + kb + c4);
            float4 ta;
            ta.x = __uint_as_float(f2tf(va.x));
            ta.y = __uint_as_float(f2tf(va.y));
            ta.z = __uint_as_float(f2tf(va.z));
            ta.w = __uint_as_float(f2tf(va.w));
            *(float4*)&sA[row][c4] = ta;
            float4 vb = *(const float4*)(B + (size_t)(n0 + row) * 512 + kb + c4);
            float4 tb;
            tb.x = __uint_as_float(f2tf(vb.x));
            tb.y = __uint_as_float(f2tf(vb.y));
            tb.z = __uint_as_float(f2tf(vb.z));
            tb.w = __uint_as_float(f2tf(vb.w));
            *(float4*)&sB[row][c4] = tb;
        }
        __syncthreads();

#pragma unroll
        for (int ks = 0; ks < 4; ks++) {
            unsigned af[4][4], bf[8][2];
#pragma unroll
            for (int mt = 0; mt < 4; mt++) {
                int r = (wm << 6) + (mt << 4) + group;
                int c = (ks << 3) + tq;
                af[mt][0] = __float_as_uint(sA[r][c]);
                af[mt][1] = __float_as_uint(sA[r + 8][c]);
                af[mt][2] = __float_as_uint(sA[r][c + 4]);
                af[mt][3] = __float_as_uint(sA[r + 8][c + 4]);
            }
#pragma unroll
            for (int nt = 0; nt < 8; nt++) {
                int r = (wn << 6) + (nt << 3) + group;
                int c = (ks << 3) + tq;
                bf[nt][0] = __float_as_uint(sB[r][c]);
                bf[nt][1] = __float_as_uint(sB[r][c + 4]);
            }
#pragma unroll
            for (int mt = 0; mt < 4; mt++)
#pragma unroll
                for (int nt = 0; nt < 8; nt++)
                    mma_tf32(acc[mt][nt], af[mt], bf[nt][0], bf[nt][1]);
        }
        __syncthreads();
    }

    // epilogue
#pragma unroll
    for (int mt = 0; mt < 4; mt++) {
#pragma unroll
        for (int nt = 0; nt < 8; nt++) {
            int m = m0 + (wm << 6) + (mt << 4) + group;
            int n = n0 + (wn << 6) + (nt << 3) + (tq << 1);
#pragma unroll
            for (int rh = 0; rh < 2; rh++) {
                int mm = m + (rh << 3);
                float v0 = acc[mt][nt][rh * 2 + 0];
                float v1 = acc[mt][nt][rh * 2 + 1];
                if (OSEL == 0) {
                    C[(size_t)mm * 512 + n]     = v0;
                    C[(size_t)mm * 512 + n + 1] = v1;
                } else {
                    int b = mm >> 12, s = mm & 4095;
                    int h = n >> 6,  d = n & 63;
                    size_t base = (((size_t)(b * NH + h)) * SEQ + s) * DH + d;
                    C[base]     = __uint_as_float(f2tf(v0));
                    C[base + 1] = __uint_as_float(f2tf(v1));
                }
            }
        }
    }
}

__global__ __launch_bounds__(128, 2)
void gemm_proj(const float* __restrict__ q, const float* __restrict__ k,
               const float* __restrict__ v, const float* __restrict__ wq,
               const float* __restrict__ wk, const float* __restrict__ wv)
{
    const float* A; const float* B; float* C;
    if (blockIdx.z == 0)      { A = q; B = wq; C = g_Qp; }
    else if (blockIdx.z == 1) { A = k; B = wk; C = g_Kp; }
    else                      { A = v; B = wv; C = g_Vp; }
    gemm_body<1>(A, B, C);
}

__global__ __launch_bounds__(128, 2)
void gemm_out(const float* __restrict__ wo, float* __restrict__ out)
{
    gemm_body<0>(g_At, wo, out);
}

// ---------------------------------------------------------------------------
// Flash attention, tf32 mma. BQ=64, BK=64, 128 threads = 4 warps.
// Warp w owns query rows [q0+16w, q0+16w+16). Q frags register-resident.
// smem: sP (Q staging, then P) 64x68 | sK 64x68 | sV 64x68  = 52224 B dynamic.
// Inputs g_Qp/g_Kp/g_Vp are pre-rounded tf32. Output g_At plain fp32 [B,S,D].
// ---------------------------------------------------------------------------
__global__ __launch_bounds__(128, 3)
void flash_tc()
{
    extern __shared__ float sm[];
    float (*sP)[68] = (float(*)[68])sm;         // 64 rows
    float (*sK)[68] = (float(*)[68])(sm + 64 * 68);
    float (*sV)[68] = (float(*)[68])(sm + 2 * 64 * 68);

    const int tid = threadIdx.x;
    const int lane = tid & 31, wid = tid >> 5;
    const int group = lane >> 2, tq = lane & 3;
    const int qb = (gridDim.x - 1) - blockIdx.x;   // heavy tiles first
    const int q0 = qb << 6;
    const int bh = blockIdx.y;

    const float* Qb = g_Qp + (size_t)bh * SEQ * DH;
    const float* Kb = g_Kp + (size_t)bh * SEQ * DH;
    const float* Vb = g_Vp + (size_t)bh * SEQ * DH;

    // stage Q tile (64x64) into sP
    {
        int r0 = tid >> 4, c4 = (tid & 15) << 2;
#pragma unroll
        for (int rr = 0; rr < 8; rr++) {
            int row = r0 + (rr << 3);
            *(float4*)&sP[row][c4] =
                *(const float4*)(Qb + (size_t)(q0 + row) * DH + c4);
        }
    }
    __syncthreads();

    // Q fragments (warp-private rows), register resident
    const int rw = wid << 4;
    unsigned qf[8][4];
#pragma unroll
    for (int ks = 0; ks < 8; ks++) {
        int c = (ks << 3) + tq;
        qf[ks][0] = __float_as_uint(sP[rw + group][c]);
        qf[ks][1] = __float_as_uint(sP[rw + group + 8][c]);
        qf[ks][2] = __float_as_uint(sP[rw + group][c + 4]);
        qf[ks][3] = __float_as_uint(sP[rw + group + 8][c + 4]);
    }

    float o[8][4];
#pragma unroll
    for (int nt = 0; nt < 8; nt++)
#pragma unroll
        for (int c = 0; c < 4; c++) o[nt][c] = 0.f;
    float mr[2] = {-1e30f, -1e30f};
    float lr[2] = {0.f, 0.f};

    const float cscale = 0.125f * 1.4426950408889634f;  // 1/sqrt(64) * log2(e)

    for (int kt = 0; kt <= qb; kt++) {
        __syncthreads();   // sK/sV reads of previous iter done
        {   // stage K (rows 0..63) and V (rows 64..127)
            int r0 = tid >> 4, c4 = (tid & 15) << 2;
            int kbase = kt << 6;
#pragma unroll
            for (int rr = 0; rr < 16; rr++) {
                int r = r0 + (rr << 3);
                if (r < 64)
                    *(float4*)&sK[r][c4] =
                        *(const float4*)(Kb + (size_t)(kbase + r) * DH + c4);
                else
                    *(float4*)&sV[r - 64][c4] =
                        *(const float4*)(Vb + (size_t)(kbase + r - 64) * DH + c4);
            }
        }
        __syncthreads();

        // S = Q @ K^T  (16 x 64 per warp)
        float s[8][4];
#pragma unroll
        for (int nt = 0; nt < 8; nt++)
#pragma unroll
            for (int c = 0; c < 4; c++) s[nt][c] = 0.f;
#pragma unroll
        for (int nt = 0; nt < 8; nt++) {
            int r = (nt << 3) + group;
#pragma unroll
            for (int ks = 0; ks < 8; ks++) {
                int c = (ks << 3) + tq;
                unsigned b0 = __float_as_uint(sK[r][c]);
                unsigned b1 = __float_as_uint(sK[r][c + 4]);
                mma_tf32(s[nt], qf[ks], b0, b1);
            }
        }

        // scale to exp2 domain + causal mask on diagonal tile
#pragma unroll
        for (int nt = 0; nt < 8; nt++)
#pragma unroll
            for (int c = 0; c < 4; c++) s[nt][c] *= cscale;
        if (kt == qb) {
            int qr0 = rw + group;       // local q row for c0/c1
            int qr1 = rw + group + 8;   // for c2/c3
#pragma unroll
            for (int nt = 0; nt < 8; nt++) {
                int kv = (nt << 3) + (tq << 1);
                if (kv > qr0)     s[nt][0] = -1e30f;
                if (kv + 1 > qr0) s[nt][1] = -1e30f;
                if (kv > qr1)     s[nt][2] = -1e30f;
                if (kv + 1 > qr1) s[nt][3] = -1e30f;
            }
        }

        // online softmax per row half (r=0: c0/c1, r=1: c2/c3)
#pragma unroll
        for (int r = 0; r < 2; r++) {
            float mx = -1e30f;
#pragma unroll
            for (int nt = 0; nt < 8; nt++)
                mx = fmaxf(mx, fmaxf(s[nt][2 * r], s[nt][2 * r + 1]));
            mx = fmaxf(mx, __shfl_xor_sync(0xffffffffu, mx, 1));
            mx = fmaxf(mx, __shfl_xor_sync(0xffffffffu, mx, 2));
            float mn = fmaxf(mr[r], mx);
            float al = ex2_(mr[r] - mn);
            mr[r] = mn;
            float rs = 0.f;
#pragma unroll
            for (int nt = 0; nt < 8; nt++) {
                float p0 = ex2_(s[nt][2 * r] - mn);
                float p1 = ex2_(s[nt][2 * r + 1] - mn);
                s[nt][2 * r] = p0;
                s[nt][2 * r + 1] = p1;
                rs += p0 + p1;
            }
            rs += __shfl_xor_sync(0xffffffffu, rs, 1);
            rs += __shfl_xor_sync(0xffffffffu, rs, 2);
            lr[r] = lr[r] * al + rs;
#pragma unroll
            for (int nt = 0; nt < 8; nt++) {
                o[nt][2 * r]     *= al;
                o[nt][2 * r + 1] *= al;
            }
        }

        // store P (tf32) into warp-private sP rows
#pragma unroll
        for (int nt = 0; nt < 8; nt++) {
            int c = (nt << 3) + (tq << 1);
            sP[rw + group][c]         = __uint_as_float(f2tf(s[nt][0]));
            sP[rw + group][c + 1]     = __uint_as_float(f2tf(s[nt][1]));
            sP[rw + group + 8][c]     = __uint_as_float(f2tf(s[nt][2]));
            sP[rw + group + 8][c + 1] = __uint_as_float(f2tf(s[nt][3]));
        }
        __syncwarp();

        // P a-frags
        unsigned pf[8][4];
#pragma unroll
        for (int ks = 0; ks < 8; ks++) {
            int c = (ks << 3) + tq;
            pf[ks][0] = __float_as_uint(sP[rw + group][c]);
            pf[ks][1] = __float_as_uint(sP[rw + group + 8][c]);
            pf[ks][2] = __float_as_uint(sP[rw + group][c + 4]);
            pf[ks][3] = __float_as_uint(sP[rw + group + 8][c + 4]);
        }

        // O += P @ V
#pragma unroll
        for (int nt = 0; nt < 8; nt++) {
#pragma unroll
            for (int ks = 0; ks < 8; ks++) {
                int kr = (ks << 3) + tq;
                int nc = (nt << 3) + group;
                unsigned b0 = __float_as_uint(sV[kr][nc]);
                unsigned b1 = __float_as_uint(sV[kr + 4][nc]);
                mma_tf32(o[nt], pf[ks], b0, b1);
            }
        }
    }

    // epilogue -> g_At [B, S, H*Dh] (plain fp32)
    const int b = bh >> 3, h = bh & 7;
#pragma unroll
    for (int r = 0; r < 2; r++) {
        int row = q0 + rw + group + (r << 3);
        float inv = 1.f / lr[r];
#pragma unroll
        for (int nt = 0; nt < 8; nt++) {
            int col = (h << 6) + (nt << 3) + (tq << 1);
            size_t base = ((size_t)b * SEQ + row) * DM + col;
            g_At[base]     = o[nt][2 * r] * inv;
            g_At[base + 1] = o[nt][2 * r + 1] * inv;
        }
    }
}

// ---------------------------------------------------------------------------
extern "C" void kernel_launch(void* const* d_in, const int* in_sizes, int n_in,
                              void* d_out, int out_size)
{
    const float* q  = (const float*)d_in[0];
    const float* k  = (const float*)d_in[1];
    const float* v  = (const float*)d_in[2];
    const float* wq = (const float*)d_in[3];
    const float* wk = (const float*)d_in[4];
    const float* wv = (const float*)d_in[5];
    const float* wo = (const float*)d_in[6];
    float* out = (float*)d_out;

    const int FLASH_SMEM = 3 * 64 * 68 * (int)sizeof(float);  // 52224
    cudaFuncSetAttribute(flash_tc, cudaFuncAttributeMaxDynamicSharedMemorySize,
                         FLASH_SMEM);

    dim3 pg(MTOT / 128, DM / 128, 3);        // 64 x 4 x 3
    gemm_proj<<<pg, 128>>>(q, k, v, wq, wk, wv);

    dim3 fg(SEQ / 64, BATCH * NH);           // 64 x 16
    flash_tc<<<fg, 128, FLASH_SMEM>>>();

    dim3 og(MTOT / 128, DM / 128);           // 64 x 4
    gemm_out<<<og, 128>>>(wo, out);
}